// round 4
// baseline (speedup 1.0000x reference)
#include <cuda_runtime.h>
#include <cstdint>

// Problem constants (shapes fixed by the dataset)
#define BSZ 4096
#define DD  512
#define HH  1024
#define TW  16
#define NEL (BSZ * HH)   // 4,194,304 = 2^22

// GEMM tiling
#define BM 128
#define BN 128
#define BK 16
#define TM 8
#define TN 8
#define NTHR 256

// Packed f32x2 helpers (Blackwell dual-rate fp32; bitwise-identical per lane)
#define PACK2(d, lo, hi) \
    asm("mov.b64 %0, {%1, %2};" : "=l"(d) : "f"(lo), "f"(hi))
#define UNPACK2(lo, hi, d) \
    asm("mov.b64 {%0, %1}, %2;" : "=f"(lo), "=f"(hi) : "l"(d))
#define FMA2(d, a, b) \
    asm("fma.rn.f32x2 %0, %1, %2, %0;" : "+l"(d) : "l"(a), "l"(b))

// ---------------------------------------------------------------------------
// Scratch (static device globals — no runtime allocation)
// ---------------------------------------------------------------------------
__device__ float g_z0[NEL];   // fc1(x), time-invariant
__device__ float g_c0[NEL];   // z0 @ lif1_win.T, time-invariant
__device__ float g_v1[NEL];
__device__ float g_i1[NEL];
__device__ float g_z1a[NEL];
__device__ float g_z1b[NEL];
__device__ float g_G2[NEL];
__device__ float g_v2[NEL];
__device__ float g_i2[NEL];
__device__ float g_z2a[NEL];
__device__ float g_z2b[NEL];
__device__ unsigned g_cnt[TW];

// ---------------------------------------------------------------------------
__global__ void init_state() {
    size_t i = (size_t)blockIdx.x * blockDim.x + threadIdx.x;
    size_t stride = (size_t)gridDim.x * blockDim.x;
    for (size_t k = i; k < (size_t)NEL; k += stride) {
        g_v1[k] = 0.f; g_i1[k] = 0.f; g_z1a[k] = 0.f;
        g_v2[k] = 0.f; g_i2[k] = 0.f; g_z2a[k] = 0.f;
    }
    if (i < TW) g_cnt[i] = 0u;
}

// ---------------------------------------------------------------------------
// Fused SGEMM:  C[M,N] = A1[M,K1] @ W1[N,K1]^T  (+ A2[M,K2] @ W2[N,K2]^T)
// mode 0: Cout = acc (+ bias[n])
// mode 1: LIF1 epilogue (cin = hoisted constant input current)
// mode 2: LIF2 epilogue (dual-GEMM) + spike count
// Mainloop uses packed fma.rn.f32x2: identical fp32 fma sequence per element
// as the scalar version -> bitwise identical results.
// ---------------------------------------------------------------------------
__global__ __launch_bounds__(NTHR, 2)
void sgemm_fused(const float* __restrict__ A1, const float* __restrict__ W1,
                 const float* __restrict__ A2, const float* __restrict__ W2,
                 const float* __restrict__ bias, const float* __restrict__ cin,
                 float* __restrict__ Cout,
                 float* __restrict__ Vst, float* __restrict__ Ist,
                 unsigned* __restrict__ cnt,
                 int K1, int K2, int N, int mode)
{
    __shared__ __align__(16) float As[BK][BM + 4];
    __shared__ __align__(16) float Bs[BK][BN + 4];

    const int tid = threadIdx.x;
    const int bn = blockIdx.x;
    const int bm = blockIdx.y;
    const int tx = tid & 15;         // 0..15 -> N microtile
    const int ty = tid >> 4;         // 0..15 -> M microtile
    const int lrow = tid >> 2;       // 0..63 loader row
    const int lcol = (tid & 3) << 2; // 0,4,8,12 loader col (float4)

    unsigned long long acc2[TM][TN / 2];
#pragma unroll
    for (int i = 0; i < TM; ++i)
#pragma unroll
        for (int j = 0; j < TN / 2; ++j) acc2[i][j] = 0ull;

    const int nt1 = K1 / BK;
    const int ntot = nt1 + (A2 ? (K2 / BK) : 0);

    for (int kt = 0; kt < ntot; ++kt) {
        const float* A; const float* W; int k0, K;
        if (kt < nt1) { A = A1; W = W1; k0 = kt * BK;         K = K1; }
        else          { A = A2; W = W2; k0 = (kt - nt1) * BK; K = K2; }

        const float* Ap = A + (size_t)(bm * BM + lrow) * K + k0 + lcol;
        const float* Wp = W + (size_t)(bn * BN + lrow) * K + k0 + lcol;
        float4 a0 = *(const float4*)Ap;
        float4 a1 = *(const float4*)(Ap + (size_t)64 * K);
        float4 b0 = *(const float4*)Wp;
        float4 b1 = *(const float4*)(Wp + (size_t)64 * K);

        __syncthreads();   // previous iteration's compute done reading smem

        As[lcol + 0][lrow] = a0.x; As[lcol + 1][lrow] = a0.y;
        As[lcol + 2][lrow] = a0.z; As[lcol + 3][lrow] = a0.w;
        As[lcol + 0][lrow + 64] = a1.x; As[lcol + 1][lrow + 64] = a1.y;
        As[lcol + 2][lrow + 64] = a1.z; As[lcol + 3][lrow + 64] = a1.w;
        Bs[lcol + 0][lrow] = b0.x; Bs[lcol + 1][lrow] = b0.y;
        Bs[lcol + 2][lrow] = b0.z; Bs[lcol + 3][lrow] = b0.w;
        Bs[lcol + 0][lrow + 64] = b1.x; Bs[lcol + 1][lrow + 64] = b1.y;
        Bs[lcol + 2][lrow + 64] = b1.z; Bs[lcol + 3][lrow + 64] = b1.w;

        __syncthreads();

#pragma unroll
        for (int k = 0; k < BK; ++k) {
            const float4 av0 = *(const float4*)&As[k][ty * TM];
            const float4 av1 = *(const float4*)&As[k][ty * TM + 4];
            const float4 bv0 = *(const float4*)&Bs[k][tx * TN];
            const float4 bv1 = *(const float4*)&Bs[k][tx * TN + 4];

            unsigned long long a2[TM], b2[TN / 2];
            PACK2(a2[0], av0.x, av0.x); PACK2(a2[1], av0.y, av0.y);
            PACK2(a2[2], av0.z, av0.z); PACK2(a2[3], av0.w, av0.w);
            PACK2(a2[4], av1.x, av1.x); PACK2(a2[5], av1.y, av1.y);
            PACK2(a2[6], av1.z, av1.z); PACK2(a2[7], av1.w, av1.w);
            PACK2(b2[0], bv0.x, bv0.y); PACK2(b2[1], bv0.z, bv0.w);
            PACK2(b2[2], bv1.x, bv1.y); PACK2(b2[3], bv1.z, bv1.w);

#pragma unroll
            for (int i = 0; i < TM; ++i)
#pragma unroll
                for (int j = 0; j < TN / 2; ++j)
                    FMA2(acc2[i][j], a2[i], b2[j]);
        }
    }

    // ---------------- epilogue ----------------
    float acc[TM][TN];
#pragma unroll
    for (int i = 0; i < TM; ++i)
#pragma unroll
        for (int j = 0; j < TN / 2; ++j)
            UNPACK2(acc[i][2 * j], acc[i][2 * j + 1], acc2[i][j]);

    const int m0 = bm * BM + ty * TM;
    const int n0 = bn * BN + tx * TN;

    if (mode == 0) {
#pragma unroll
        for (int i = 0; i < TM; ++i) {
            size_t row = (size_t)(m0 + i) * N + n0;
#pragma unroll
            for (int j = 0; j < TN; ++j) {
                float v = acc[i][j];
                if (bias) v += bias[n0 + j];
                Cout[row + j] = v;
            }
        }
    } else {
        unsigned spikes = 0;
#pragma unroll
        for (int i = 0; i < TM; ++i) {
            size_t row = (size_t)(m0 + i) * N + n0;
#pragma unroll
            for (int j = 0; j < TN; ++j) {
                size_t idx = row + j;
                float vold = Vst[idx];
                float iold = Ist[idx];
                float vdec = vold + 0.1f * (iold - vold);     // dt*tau_mem_inv
                float z = (vdec > 1.0f) ? 1.0f : 0.0f;        // v_th = 1
                Vst[idx] = (1.0f - z) * vdec;                 // v_reset = 0
                float idec = iold * 0.8f;                     // 1 - dt*tau_syn_inv
                float inew = (mode == 1) ? ((idec + cin[idx]) + acc[i][j])
                                         : (idec + acc[i][j]);
                Ist[idx] = inew;
                Cout[idx] = z;
                spikes += (unsigned)z;
            }
        }
        if (mode == 2) {
#pragma unroll
            for (int o = 16; o; o >>= 1)
                spikes += __shfl_xor_sync(0xFFFFFFFFu, spikes, o);
            if ((tid & 31) == 0) atomicAdd(cnt, spikes);
        }
    }
}

// ---------------------------------------------------------------------------
// Final: copy last z2 to output, compute firing-rate scalar (bit-exact:
// counts are integers, mean = count * 2^-22, sum in scan order, * 1/16).
// ---------------------------------------------------------------------------
__global__ void finalize(const float* __restrict__ zlast,
                         const unsigned* __restrict__ cnt,
                         float* __restrict__ out, int n, int out_size)
{
    size_t i = (size_t)blockIdx.x * blockDim.x + threadIdx.x;
    size_t stride = (size_t)gridDim.x * blockDim.x;
    for (size_t k = i; k < (size_t)n; k += stride) out[k] = zlast[k];
    if (i == 0 && out_size > n) {
        float rs = 0.f;
        for (int t = 0; t < TW; ++t)
            rs += (float)cnt[t] * (1.0f / 4194304.0f);   // exact: /2^22
        out[n] = rs * (1.0f / 16.0f);                     // inv_T, exact
    }
}

// ---------------------------------------------------------------------------
extern "C" void kernel_launch(void* const* d_in, const int* in_sizes, int n_in,
                              void* d_out, int out_size)
{
    const float* x     = (const float*)d_in[0];
    const float* fc1w  = (const float*)d_in[1];
    const float* fc1b  = (const float*)d_in[2];
    const float* w1in  = (const float*)d_in[3];
    const float* w1rec = (const float*)d_in[4];
    const float* fc2w  = (const float*)d_in[5];
    const float* fc2b  = (const float*)d_in[6];
    const float* w2in  = (const float*)d_in[7];
    const float* w2rec = (const float*)d_in[8];
    (void)in_sizes; (void)n_in;

    float *z0, *c0, *v1, *i1, *z1a, *z1b, *G2, *v2, *i2, *z2a, *z2b;
    unsigned* cnt;
    cudaGetSymbolAddress((void**)&z0,  g_z0);
    cudaGetSymbolAddress((void**)&c0,  g_c0);
    cudaGetSymbolAddress((void**)&v1,  g_v1);
    cudaGetSymbolAddress((void**)&i1,  g_i1);
    cudaGetSymbolAddress((void**)&z1a, g_z1a);
    cudaGetSymbolAddress((void**)&z1b, g_z1b);
    cudaGetSymbolAddress((void**)&G2,  g_G2);
    cudaGetSymbolAddress((void**)&v2,  g_v2);
    cudaGetSymbolAddress((void**)&i2,  g_i2);
    cudaGetSymbolAddress((void**)&z2a, g_z2a);
    cudaGetSymbolAddress((void**)&z2b, g_z2b);
    cudaGetSymbolAddress((void**)&cnt, g_cnt);

    dim3 grid(HH / BN, BSZ / BM);   // (8, 32) = 256 blocks

    init_state<<<256, 256>>>();

    // z0 = x @ fc1_w^T + fc1_b   (K = 512)
    sgemm_fused<<<grid, NTHR>>>(x, fc1w, nullptr, nullptr, fc1b, nullptr,
                                z0, nullptr, nullptr, nullptr,
                                DD, 0, HH, 0);
    // c0 = z0 @ lif1_win^T       (time-invariant input current, hoisted)
    sgemm_fused<<<grid, NTHR>>>(z0, w1in, nullptr, nullptr, nullptr, nullptr,
                                c0, nullptr, nullptr, nullptr,
                                HH, 0, HH, 0);

    for (int t = 0; t < TW; ++t) {
        float* z1o = (t & 1) ? z1b : z1a;
        float* z1n = (t & 1) ? z1a : z1b;
        float* z2o = (t & 1) ? z2b : z2a;
        float* z2n = (t & 1) ? z2a : z2b;

        // LIF1: acc = z1_old @ w1rec^T ; epilogue: decay/spike/reset,
        //       i1 = (0.8*i1 + c0) + acc, writes z1_new
        sgemm_fused<<<grid, NTHR>>>(z1o, w1rec, nullptr, nullptr, nullptr, c0,
                                    z1n, v1, i1, nullptr,
                                    HH, 0, HH, 1);
        // G2 = z1_new @ fc2_w^T + fc2_b
        sgemm_fused<<<grid, NTHR>>>(z1n, fc2w, nullptr, nullptr, fc2b, nullptr,
                                    G2, nullptr, nullptr, nullptr,
                                    HH, 0, HH, 0);
        // LIF2: acc = G2 @ w2in^T + z2_old @ w2rec^T (dual-K GEMM);
        //       epilogue updates v2/i2, writes z2_new, counts spikes
        sgemm_fused<<<grid, NTHR>>>(G2, w2in, z2o, w2rec, nullptr, nullptr,
                                    z2n, v2, i2, cnt + t,
                                    HH, HH, HH, 2);
    }

    // t = 15 (odd) wrote z2_new into z2a
    finalize<<<512, 256>>>(z2a, cnt, (float*)d_out, NEL, out_size);
}

// round 5
// speedup vs baseline: 1.0001x; 1.0001x over previous
#include <cuda_runtime.h>
#include <cstdint>

// Problem constants (shapes fixed by the dataset)
#define BSZ 4096
#define DD  512
#define HH  1024
#define TW  16
#define NEL (BSZ * HH)   // 4,194,304 = 2^22

// GEMM tiling
#define BM 128
#define BN 128
#define BK 16
#define TM 8
#define TN 8
#define NTHR 256

// Packed f32x2 helpers (Blackwell dual-rate fp32; bitwise-identical per lane)
#define PACK2(d, lo, hi) \
    asm("mov.b64 %0, {%1, %2};" : "=l"(d) : "f"(lo), "f"(hi))
#define UNPACK2(lo, hi, d) \
    asm("mov.b64 {%0, %1}, %2;" : "=f"(lo), "=f"(hi) : "l"(d))
#define FMA2(d, a, b) \
    asm("fma.rn.f32x2 %0, %1, %2, %0;" : "+l"(d) : "l"(a), "l"(b))

// ---------------------------------------------------------------------------
// Scratch (static device globals — no runtime allocation)
// ---------------------------------------------------------------------------
__device__ float g_z0[NEL];   // fc1(x), time-invariant
__device__ float g_c0[NEL];   // z0 @ lif1_win.T, time-invariant
__device__ float g_v1[NEL];
__device__ float g_i1[NEL];
__device__ float g_z1a[NEL];
__device__ float g_z1b[NEL];
__device__ float g_G2[NEL];
__device__ float g_v2[NEL];
__device__ float g_i2[NEL];
__device__ float g_z2a[NEL];
__device__ float g_z2b[NEL];
__device__ unsigned g_cnt[TW];

// ---------------------------------------------------------------------------
__global__ void init_state() {
    size_t i = (size_t)blockIdx.x * blockDim.x + threadIdx.x;
    size_t stride = (size_t)gridDim.x * blockDim.x;
    for (size_t k = i; k < (size_t)NEL; k += stride) {
        g_v1[k] = 0.f; g_i1[k] = 0.f; g_z1a[k] = 0.f;
        g_v2[k] = 0.f; g_i2[k] = 0.f; g_z2a[k] = 0.f;
    }
    if (i < TW) g_cnt[i] = 0u;
}

// ---------------------------------------------------------------------------
// Fused SGEMM:  C[M,N] = A1[M,K1] @ W1[N,K1]^T  (+ A2[M,K2] @ W2[N,K2]^T)
// mode 0: Cout = acc (+ bias[n])
// mode 1: LIF1 epilogue (cin = hoisted constant input current)
// mode 2: LIF2 epilogue (dual-GEMM) + spike count
// Mainloop uses packed fma.rn.f32x2: identical fp32 fma sequence per element
// as the scalar version -> bitwise identical results.
// ---------------------------------------------------------------------------
__global__ __launch_bounds__(NTHR, 2)
void sgemm_fused(const float* __restrict__ A1, const float* __restrict__ W1,
                 const float* __restrict__ A2, const float* __restrict__ W2,
                 const float* __restrict__ bias, const float* __restrict__ cin,
                 float* __restrict__ Cout,
                 float* __restrict__ Vst, float* __restrict__ Ist,
                 unsigned* __restrict__ cnt,
                 int K1, int K2, int N, int mode)
{
    __shared__ __align__(16) float As[BK][BM + 4];
    __shared__ __align__(16) float Bs[BK][BN + 4];

    const int tid = threadIdx.x;
    const int bn = blockIdx.x;
    const int bm = blockIdx.y;
    const int tx = tid & 15;         // 0..15 -> N microtile
    const int ty = tid >> 4;         // 0..15 -> M microtile
    const int lrow = tid >> 2;       // 0..63 loader row
    const int lcol = (tid & 3) << 2; // 0,4,8,12 loader col (float4)

    unsigned long long acc2[TM][TN / 2];
#pragma unroll
    for (int i = 0; i < TM; ++i)
#pragma unroll
        for (int j = 0; j < TN / 2; ++j) acc2[i][j] = 0ull;

    const int nt1 = K1 / BK;
    const int ntot = nt1 + (A2 ? (K2 / BK) : 0);

    for (int kt = 0; kt < ntot; ++kt) {
        const float* A; const float* W; int k0, K;
        if (kt < nt1) { A = A1; W = W1; k0 = kt * BK;         K = K1; }
        else          { A = A2; W = W2; k0 = (kt - nt1) * BK; K = K2; }

        const float* Ap = A + (size_t)(bm * BM + lrow) * K + k0 + lcol;
        const float* Wp = W + (size_t)(bn * BN + lrow) * K + k0 + lcol;
        float4 a0 = *(const float4*)Ap;
        float4 a1 = *(const float4*)(Ap + (size_t)64 * K);
        float4 b0 = *(const float4*)Wp;
        float4 b1 = *(const float4*)(Wp + (size_t)64 * K);

        __syncthreads();   // previous iteration's compute done reading smem

        As[lcol + 0][lrow] = a0.x; As[lcol + 1][lrow] = a0.y;
        As[lcol + 2][lrow] = a0.z; As[lcol + 3][lrow] = a0.w;
        As[lcol + 0][lrow + 64] = a1.x; As[lcol + 1][lrow + 64] = a1.y;
        As[lcol + 2][lrow + 64] = a1.z; As[lcol + 3][lrow + 64] = a1.w;
        Bs[lcol + 0][lrow] = b0.x; Bs[lcol + 1][lrow] = b0.y;
        Bs[lcol + 2][lrow] = b0.z; Bs[lcol + 3][lrow] = b0.w;
        Bs[lcol + 0][lrow + 64] = b1.x; Bs[lcol + 1][lrow + 64] = b1.y;
        Bs[lcol + 2][lrow + 64] = b1.z; Bs[lcol + 3][lrow + 64] = b1.w;

        __syncthreads();

#pragma unroll
        for (int k = 0; k < BK; ++k) {
            const float4 av0 = *(const float4*)&As[k][ty * TM];
            const float4 av1 = *(const float4*)&As[k][ty * TM + 4];
            const float4 bv0 = *(const float4*)&Bs[k][tx * TN];
            const float4 bv1 = *(const float4*)&Bs[k][tx * TN + 4];

            unsigned long long a2[TM], b2[TN / 2];
            PACK2(a2[0], av0.x, av0.x); PACK2(a2[1], av0.y, av0.y);
            PACK2(a2[2], av0.z, av0.z); PACK2(a2[3], av0.w, av0.w);
            PACK2(a2[4], av1.x, av1.x); PACK2(a2[5], av1.y, av1.y);
            PACK2(a2[6], av1.z, av1.z); PACK2(a2[7], av1.w, av1.w);
            PACK2(b2[0], bv0.x, bv0.y); PACK2(b2[1], bv0.z, bv0.w);
            PACK2(b2[2], bv1.x, bv1.y); PACK2(b2[3], bv1.z, bv1.w);

#pragma unroll
            for (int i = 0; i < TM; ++i)
#pragma unroll
                for (int j = 0; j < TN / 2; ++j)
                    FMA2(acc2[i][j], a2[i], b2[j]);
        }
    }

    // ---------------- epilogue ----------------
    float acc[TM][TN];
#pragma unroll
    for (int i = 0; i < TM; ++i)
#pragma unroll
        for (int j = 0; j < TN / 2; ++j)
            UNPACK2(acc[i][2 * j], acc[i][2 * j + 1], acc2[i][j]);

    const int m0 = bm * BM + ty * TM;
    const int n0 = bn * BN + tx * TN;

    if (mode == 0) {
#pragma unroll
        for (int i = 0; i < TM; ++i) {
            size_t row = (size_t)(m0 + i) * N + n0;
#pragma unroll
            for (int j = 0; j < TN; ++j) {
                float v = acc[i][j];
                if (bias) v += bias[n0 + j];
                Cout[row + j] = v;
            }
        }
    } else {
        unsigned spikes = 0;
#pragma unroll
        for (int i = 0; i < TM; ++i) {
            size_t row = (size_t)(m0 + i) * N + n0;
#pragma unroll
            for (int j = 0; j < TN; ++j) {
                size_t idx = row + j;
                float vold = Vst[idx];
                float iold = Ist[idx];
                float vdec = vold + 0.1f * (iold - vold);     // dt*tau_mem_inv
                float z = (vdec > 1.0f) ? 1.0f : 0.0f;        // v_th = 1
                Vst[idx] = (1.0f - z) * vdec;                 // v_reset = 0
                float idec = iold * 0.8f;                     // 1 - dt*tau_syn_inv
                float inew = (mode == 1) ? ((idec + cin[idx]) + acc[i][j])
                                         : (idec + acc[i][j]);
                Ist[idx] = inew;
                Cout[idx] = z;
                spikes += (unsigned)z;
            }
        }
        if (mode == 2) {
#pragma unroll
            for (int o = 16; o; o >>= 1)
                spikes += __shfl_xor_sync(0xFFFFFFFFu, spikes, o);
            if ((tid & 31) == 0) atomicAdd(cnt, spikes);
        }
    }
}

// ---------------------------------------------------------------------------
// Final: copy last z2 to output, compute firing-rate scalar (bit-exact:
// counts are integers, mean = count * 2^-22, sum in scan order, * 1/16).
// ---------------------------------------------------------------------------
__global__ void finalize(const float* __restrict__ zlast,
                         const unsigned* __restrict__ cnt,
                         float* __restrict__ out, int n, int out_size)
{
    size_t i = (size_t)blockIdx.x * blockDim.x + threadIdx.x;
    size_t stride = (size_t)gridDim.x * blockDim.x;
    for (size_t k = i; k < (size_t)n; k += stride) out[k] = zlast[k];
    if (i == 0 && out_size > n) {
        float rs = 0.f;
        for (int t = 0; t < TW; ++t)
            rs += (float)cnt[t] * (1.0f / 4194304.0f);   // exact: /2^22
        out[n] = rs * (1.0f / 16.0f);                     // inv_T, exact
    }
}

// ---------------------------------------------------------------------------
extern "C" void kernel_launch(void* const* d_in, const int* in_sizes, int n_in,
                              void* d_out, int out_size)
{
    const float* x     = (const float*)d_in[0];
    const float* fc1w  = (const float*)d_in[1];
    const float* fc1b  = (const float*)d_in[2];
    const float* w1in  = (const float*)d_in[3];
    const float* w1rec = (const float*)d_in[4];
    const float* fc2w  = (const float*)d_in[5];
    const float* fc2b  = (const float*)d_in[6];
    const float* w2in  = (const float*)d_in[7];
    const float* w2rec = (const float*)d_in[8];
    (void)in_sizes; (void)n_in;

    float *z0, *c0, *v1, *i1, *z1a, *z1b, *G2, *v2, *i2, *z2a, *z2b;
    unsigned* cnt;
    cudaGetSymbolAddress((void**)&z0,  g_z0);
    cudaGetSymbolAddress((void**)&c0,  g_c0);
    cudaGetSymbolAddress((void**)&v1,  g_v1);
    cudaGetSymbolAddress((void**)&i1,  g_i1);
    cudaGetSymbolAddress((void**)&z1a, g_z1a);
    cudaGetSymbolAddress((void**)&z1b, g_z1b);
    cudaGetSymbolAddress((void**)&G2,  g_G2);
    cudaGetSymbolAddress((void**)&v2,  g_v2);
    cudaGetSymbolAddress((void**)&i2,  g_i2);
    cudaGetSymbolAddress((void**)&z2a, g_z2a);
    cudaGetSymbolAddress((void**)&z2b, g_z2b);
    cudaGetSymbolAddress((void**)&cnt, g_cnt);

    dim3 grid(HH / BN, BSZ / BM);   // (8, 32) = 256 blocks

    init_state<<<256, 256>>>();

    // z0 = x @ fc1_w^T + fc1_b   (K = 512)
    sgemm_fused<<<grid, NTHR>>>(x, fc1w, nullptr, nullptr, fc1b, nullptr,
                                z0, nullptr, nullptr, nullptr,
                                DD, 0, HH, 0);
    // c0 = z0 @ lif1_win^T       (time-invariant input current, hoisted)
    sgemm_fused<<<grid, NTHR>>>(z0, w1in, nullptr, nullptr, nullptr, nullptr,
                                c0, nullptr, nullptr, nullptr,
                                HH, 0, HH, 0);

    for (int t = 0; t < TW; ++t) {
        float* z1o = (t & 1) ? z1b : z1a;
        float* z1n = (t & 1) ? z1a : z1b;
        float* z2o = (t & 1) ? z2b : z2a;
        float* z2n = (t & 1) ? z2a : z2b;

        // LIF1: acc = z1_old @ w1rec^T ; epilogue: decay/spike/reset,
        //       i1 = (0.8*i1 + c0) + acc, writes z1_new
        sgemm_fused<<<grid, NTHR>>>(z1o, w1rec, nullptr, nullptr, nullptr, c0,
                                    z1n, v1, i1, nullptr,
                                    HH, 0, HH, 1);
        // G2 = z1_new @ fc2_w^T + fc2_b
        sgemm_fused<<<grid, NTHR>>>(z1n, fc2w, nullptr, nullptr, fc2b, nullptr,
                                    G2, nullptr, nullptr, nullptr,
                                    HH, 0, HH, 0);
        // LIF2: acc = G2 @ w2in^T + z2_old @ w2rec^T (dual-K GEMM);
        //       epilogue updates v2/i2, writes z2_new, counts spikes
        sgemm_fused<<<grid, NTHR>>>(G2, w2in, z2o, w2rec, nullptr, nullptr,
                                    z2n, v2, i2, cnt + t,
                                    HH, HH, HH, 2);
    }

    // t = 15 (odd) wrote z2_new into z2a
    finalize<<<512, 256>>>(z2a, cnt, (float*)d_out, NEL, out_size);
}

// round 6
// speedup vs baseline: 1.0357x; 1.0356x over previous
#include <cuda_runtime.h>
#include <cstdint>

// Problem constants (shapes fixed by the dataset)
#define BSZ 4096
#define DD  512
#define HH  1024
#define TW  16
#define NEL (BSZ * HH)   // 4,194,304 = 2^22

// GEMM tiling
#define BM 128
#define BN 128
#define BK 16
#define TM 8
#define TN 8
#define NTHR 256

// ---------------------------------------------------------------------------
// Scratch (static device globals — no runtime allocation)
// ---------------------------------------------------------------------------
__device__ float g_z0[NEL];   // fc1(x), time-invariant
__device__ float g_c0[NEL];   // z0 @ lif1_win.T, time-invariant
__device__ float g_v1[NEL];
__device__ float g_i1[NEL];
__device__ float g_z1a[NEL];
__device__ float g_z1b[NEL];
__device__ float g_G2[NEL];
__device__ float g_v2[NEL];
__device__ float g_i2[NEL];
__device__ float g_z2a[NEL];
__device__ float g_z2b[NEL];
__device__ unsigned g_cnt[TW];

// ---------------------------------------------------------------------------
__global__ void init_state() {
    size_t i = (size_t)blockIdx.x * blockDim.x + threadIdx.x;
    size_t stride = (size_t)gridDim.x * blockDim.x;
    for (size_t k = i; k < (size_t)NEL; k += stride) {
        g_v1[k] = 0.f; g_i1[k] = 0.f; g_z1a[k] = 0.f;
        g_v2[k] = 0.f; g_i2[k] = 0.f; g_z2a[k] = 0.f;
    }
    if (i < TW) g_cnt[i] = 0u;
}

// ---------------------------------------------------------------------------
// Fused SGEMM:  C[M,N] = A1[M,K1] @ W1[N,K1]^T  (+ A2[M,K2] @ W2[N,K2]^T)
// mode 0: Cout = acc (+ bias[n])
// mode 1: LIF1 epilogue (cin = hoisted constant input current)
// mode 2: LIF2 epilogue (dual-GEMM) + spike count
//
// Double-buffered smem pipeline: one __syncthreads per k-tile; global-load
// latency for tile t+1 is hidden behind the 1024-FMA compute of tile t.
// FMA order per output element is identical to the R3 kernel (bit-exact).
// ---------------------------------------------------------------------------
__global__ __launch_bounds__(NTHR, 2)
void sgemm_fused(const float* __restrict__ A1, const float* __restrict__ W1,
                 const float* __restrict__ A2, const float* __restrict__ W2,
                 const float* __restrict__ bias, const float* __restrict__ cin,
                 float* __restrict__ Cout,
                 float* __restrict__ Vst, float* __restrict__ Ist,
                 unsigned* __restrict__ cnt,
                 int K1, int K2, int N, int mode)
{
    __shared__ __align__(16) float As[2][BK][BM + 4];
    __shared__ __align__(16) float Bs[2][BK][BN + 4];

    const int tid = threadIdx.x;
    const int bn = blockIdx.x;
    const int bm = blockIdx.y;
    const int tx = tid & 15;         // 0..15 -> N microtile
    const int ty = tid >> 4;         // 0..15 -> M microtile
    const int lrow = tid >> 2;       // 0..63 loader row
    const int lcol = (tid & 3) << 2; // 0,4,8,12 loader col (float4)

    float acc[TM][TN];
#pragma unroll
    for (int i = 0; i < TM; ++i)
#pragma unroll
        for (int j = 0; j < TN; ++j) acc[i][j] = 0.f;

    const int nt1 = K1 / BK;
    const int ntot = nt1 + (A2 ? (K2 / BK) : 0);

    float4 ra0, ra1, rb0, rb1;   // staging registers

    // ---- loader helpers ----
    #define LDG_TILE(kt)                                                       \
        do {                                                                   \
            const float* A_; const float* W_; int k0_, K_;                     \
            if ((kt) < nt1) { A_ = A1; W_ = W1; k0_ = (kt) * BK; K_ = K1; }    \
            else { A_ = A2; W_ = W2; k0_ = ((kt) - nt1) * BK; K_ = K2; }       \
            const float* Ap = A_ + (size_t)(bm * BM + lrow) * K_ + k0_ + lcol; \
            const float* Wp = W_ + (size_t)(bn * BN + lrow) * K_ + k0_ + lcol; \
            ra0 = *(const float4*)Ap;                                          \
            ra1 = *(const float4*)(Ap + (size_t)64 * K_);                      \
            rb0 = *(const float4*)Wp;                                          \
            rb1 = *(const float4*)(Wp + (size_t)64 * K_);                      \
        } while (0)

    #define STS_TILE(buf)                                                      \
        do {                                                                   \
            As[buf][lcol + 0][lrow] = ra0.x; As[buf][lcol + 1][lrow] = ra0.y;  \
            As[buf][lcol + 2][lrow] = ra0.z; As[buf][lcol + 3][lrow] = ra0.w;  \
            As[buf][lcol + 0][lrow + 64] = ra1.x;                              \
            As[buf][lcol + 1][lrow + 64] = ra1.y;                              \
            As[buf][lcol + 2][lrow + 64] = ra1.z;                              \
            As[buf][lcol + 3][lrow + 64] = ra1.w;                              \
            Bs[buf][lcol + 0][lrow] = rb0.x; Bs[buf][lcol + 1][lrow] = rb0.y;  \
            Bs[buf][lcol + 2][lrow] = rb0.z; Bs[buf][lcol + 3][lrow] = rb0.w;  \
            Bs[buf][lcol + 0][lrow + 64] = rb1.x;                              \
            Bs[buf][lcol + 1][lrow + 64] = rb1.y;                              \
            Bs[buf][lcol + 2][lrow + 64] = rb1.z;                              \
            Bs[buf][lcol + 3][lrow + 64] = rb1.w;                              \
        } while (0)

    // ---- prologue: stage tile 0 ----
    LDG_TILE(0);
    STS_TILE(0);
    __syncthreads();

    for (int kt = 0; kt < ntot; ++kt) {
        const int cur = kt & 1;
        const bool more = (kt + 1 < ntot);

        if (more) LDG_TILE(kt + 1);   // in flight during compute below

#pragma unroll
        for (int k = 0; k < BK; ++k) {
            const float4 av0 = *(const float4*)&As[cur][k][ty * TM];
            const float4 av1 = *(const float4*)&As[cur][k][ty * TM + 4];
            const float4 bv0 = *(const float4*)&Bs[cur][k][tx * TN];
            const float4 bv1 = *(const float4*)&Bs[cur][k][tx * TN + 4];
            float a[TM] = {av0.x, av0.y, av0.z, av0.w,
                           av1.x, av1.y, av1.z, av1.w};
            float b[TN] = {bv0.x, bv0.y, bv0.z, bv0.w,
                           bv1.x, bv1.y, bv1.z, bv1.w};
#pragma unroll
            for (int i = 0; i < TM; ++i)
#pragma unroll
                for (int j = 0; j < TN; ++j)
                    acc[i][j] += a[i] * b[j];
        }

        if (more) {
            STS_TILE(cur ^ 1);   // buffer last read at kt-1: all warps passed
            __syncthreads();     // the previous barrier after finishing it
        }
    }

    // ---------------- epilogue ----------------
    const int m0 = bm * BM + ty * TM;
    const int n0 = bn * BN + tx * TN;

    if (mode == 0) {
#pragma unroll
        for (int i = 0; i < TM; ++i) {
            size_t row = (size_t)(m0 + i) * N + n0;
#pragma unroll
            for (int j = 0; j < TN; ++j) {
                float v = acc[i][j];
                if (bias) v += bias[n0 + j];
                Cout[row + j] = v;
            }
        }
    } else {
        unsigned spikes = 0;
#pragma unroll
        for (int i = 0; i < TM; ++i) {
            size_t row = (size_t)(m0 + i) * N + n0;
#pragma unroll
            for (int j = 0; j < TN; ++j) {
                size_t idx = row + j;
                float vold = Vst[idx];
                float iold = Ist[idx];
                float vdec = vold + 0.1f * (iold - vold);     // dt*tau_mem_inv
                float z = (vdec > 1.0f) ? 1.0f : 0.0f;        // v_th = 1
                Vst[idx] = (1.0f - z) * vdec;                 // v_reset = 0
                float idec = iold * 0.8f;                     // 1 - dt*tau_syn_inv
                float inew = (mode == 1) ? ((idec + cin[idx]) + acc[i][j])
                                         : (idec + acc[i][j]);
                Ist[idx] = inew;
                Cout[idx] = z;
                spikes += (unsigned)z;
            }
        }
        if (mode == 2) {
#pragma unroll
            for (int o = 16; o; o >>= 1)
                spikes += __shfl_xor_sync(0xFFFFFFFFu, spikes, o);
            if ((tid & 31) == 0) atomicAdd(cnt, spikes);
        }
    }
}

// ---------------------------------------------------------------------------
// Final: copy last z2 to output, compute firing-rate scalar (bit-exact:
// counts are integers, mean = count * 2^-22, sum in scan order, * 1/16).
// ---------------------------------------------------------------------------
__global__ void finalize(const float* __restrict__ zlast,
                         const unsigned* __restrict__ cnt,
                         float* __restrict__ out, int n, int out_size)
{
    size_t i = (size_t)blockIdx.x * blockDim.x + threadIdx.x;
    size_t stride = (size_t)gridDim.x * blockDim.x;
    for (size_t k = i; k < (size_t)n; k += stride) out[k] = zlast[k];
    if (i == 0 && out_size > n) {
        float rs = 0.f;
        for (int t = 0; t < TW; ++t)
            rs += (float)cnt[t] * (1.0f / 4194304.0f);   // exact: /2^22
        out[n] = rs * (1.0f / 16.0f);                     // inv_T, exact
    }
}

// ---------------------------------------------------------------------------
extern "C" void kernel_launch(void* const* d_in, const int* in_sizes, int n_in,
                              void* d_out, int out_size)
{
    const float* x     = (const float*)d_in[0];
    const float* fc1w  = (const float*)d_in[1];
    const float* fc1b  = (const float*)d_in[2];
    const float* w1in  = (const float*)d_in[3];
    const float* w1rec = (const float*)d_in[4];
    const float* fc2w  = (const float*)d_in[5];
    const float* fc2b  = (const float*)d_in[6];
    const float* w2in  = (const float*)d_in[7];
    const float* w2rec = (const float*)d_in[8];
    (void)in_sizes; (void)n_in;

    float *z0, *c0, *v1, *i1, *z1a, *z1b, *G2, *v2, *i2, *z2a, *z2b;
    unsigned* cnt;
    cudaGetSymbolAddress((void**)&z0,  g_z0);
    cudaGetSymbolAddress((void**)&c0,  g_c0);
    cudaGetSymbolAddress((void**)&v1,  g_v1);
    cudaGetSymbolAddress((void**)&i1,  g_i1);
    cudaGetSymbolAddress((void**)&z1a, g_z1a);
    cudaGetSymbolAddress((void**)&z1b, g_z1b);
    cudaGetSymbolAddress((void**)&G2,  g_G2);
    cudaGetSymbolAddress((void**)&v2,  g_v2);
    cudaGetSymbolAddress((void**)&i2,  g_i2);
    cudaGetSymbolAddress((void**)&z2a, g_z2a);
    cudaGetSymbolAddress((void**)&z2b, g_z2b);
    cudaGetSymbolAddress((void**)&cnt, g_cnt);

    dim3 grid(HH / BN, BSZ / BM);   // (8, 32) = 256 blocks, single wave

    init_state<<<256, 256>>>();

    // z0 = x @ fc1_w^T + fc1_b   (K = 512)
    sgemm_fused<<<grid, NTHR>>>(x, fc1w, nullptr, nullptr, fc1b, nullptr,
                                z0, nullptr, nullptr, nullptr,
                                DD, 0, HH, 0);
    // c0 = z0 @ lif1_win^T       (time-invariant input current, hoisted)
    sgemm_fused<<<grid, NTHR>>>(z0, w1in, nullptr, nullptr, nullptr, nullptr,
                                c0, nullptr, nullptr, nullptr,
                                HH, 0, HH, 0);

    for (int t = 0; t < TW; ++t) {
        float* z1o = (t & 1) ? z1b : z1a;
        float* z1n = (t & 1) ? z1a : z1b;
        float* z2o = (t & 1) ? z2b : z2a;
        float* z2n = (t & 1) ? z2a : z2b;

        // LIF1: acc = z1_old @ w1rec^T ; epilogue: decay/spike/reset,
        //       i1 = (0.8*i1 + c0) + acc, writes z1_new
        sgemm_fused<<<grid, NTHR>>>(z1o, w1rec, nullptr, nullptr, nullptr, c0,
                                    z1n, v1, i1, nullptr,
                                    HH, 0, HH, 1);
        // G2 = z1_new @ fc2_w^T + fc2_b
        sgemm_fused<<<grid, NTHR>>>(z1n, fc2w, nullptr, nullptr, fc2b, nullptr,
                                    G2, nullptr, nullptr, nullptr,
                                    HH, 0, HH, 0);
        // LIF2: acc = G2 @ w2in^T + z2_old @ w2rec^T (dual-K GEMM);
        //       epilogue updates v2/i2, writes z2_new, counts spikes
        sgemm_fused<<<grid, NTHR>>>(G2, w2in, z2o, w2rec, nullptr, nullptr,
                                    z2n, v2, i2, cnt + t,
                                    HH, HH, HH, 2);
    }

    // t = 15 (odd) wrote z2_new into z2a
    finalize<<<512, 256>>>(z2a, cnt, (float*)d_out, NEL, out_size);
}

// round 7
// speedup vs baseline: 1.0479x; 1.0118x over previous
#include <cuda_runtime.h>
#include <cstdint>

// Problem constants (shapes fixed by the dataset)
#define BSZ 4096
#define DD  512
#define HH  1024
#define TW  16
#define NEL (BSZ * HH)   // 4,194,304 = 2^22

// GEMM tiling
#define BM 128
#define BN 128
#define BK 16
#define TM 8
#define TN 8
#define NTHR 256

// ---------------------------------------------------------------------------
// Scratch (static device globals — no runtime allocation)
// ---------------------------------------------------------------------------
__device__ float g_z0[NEL];   // fc1(x), time-invariant
__device__ float g_c0[NEL];   // z0 @ lif1_win.T, time-invariant
__device__ float g_v1[NEL];
__device__ float g_i1[NEL];
__device__ float g_z1a[NEL];
__device__ float g_z1b[NEL];
__device__ float g_G2[NEL];
__device__ float g_v2[NEL];
__device__ float g_i2[NEL];
__device__ float g_z2a[NEL];
__device__ float g_z2b[NEL];
__device__ unsigned g_cnt[TW];

// ---------------------------------------------------------------------------
__global__ void init_state() {
    size_t i = (size_t)blockIdx.x * blockDim.x + threadIdx.x;
    size_t stride = (size_t)gridDim.x * blockDim.x;
    for (size_t k = i; k < (size_t)NEL; k += stride) {
        g_v1[k] = 0.f; g_i1[k] = 0.f; g_z1a[k] = 0.f;
        g_v2[k] = 0.f; g_i2[k] = 0.f; g_z2a[k] = 0.f;
    }
    if (i < TW) g_cnt[i] = 0u;
}

// ---------------------------------------------------------------------------
// Fused SGEMM:  C[M,N] = A1[M,K1] @ W1[N,K1]^T  (+ A2[M,K2] @ W2[N,K2]^T)
// mode 0: Cout = acc (+ bias[n])
// mode 1: LIF1 epilogue (cin = hoisted constant input current)
// mode 2: LIF2 epilogue (dual-GEMM) + spike count
//
// Double-buffered smem pipeline: one __syncthreads per k-tile; global-load
// latency for tile t+1 is hidden behind the 1024-FMA compute of tile t.
// FMA order per output element is identical to the R3 kernel (bit-exact).
// ---------------------------------------------------------------------------
__global__ __launch_bounds__(NTHR, 2)
void sgemm_fused(const float* __restrict__ A1, const float* __restrict__ W1,
                 const float* __restrict__ A2, const float* __restrict__ W2,
                 const float* __restrict__ bias, const float* __restrict__ cin,
                 float* __restrict__ Cout,
                 float* __restrict__ Vst, float* __restrict__ Ist,
                 unsigned* __restrict__ cnt,
                 int K1, int K2, int N, int mode)
{
    __shared__ __align__(16) float As[2][BK][BM + 4];
    __shared__ __align__(16) float Bs[2][BK][BN + 4];

    const int tid = threadIdx.x;
    const int bn = blockIdx.x;
    const int bm = blockIdx.y;
    const int tx = tid & 15;         // 0..15 -> N microtile
    const int ty = tid >> 4;         // 0..15 -> M microtile
    const int lrow = tid >> 2;       // 0..63 loader row
    const int lcol = (tid & 3) << 2; // 0,4,8,12 loader col (float4)

    float acc[TM][TN];
#pragma unroll
    for (int i = 0; i < TM; ++i)
#pragma unroll
        for (int j = 0; j < TN; ++j) acc[i][j] = 0.f;

    const int nt1 = K1 / BK;
    const int ntot = nt1 + (A2 ? (K2 / BK) : 0);

    float4 ra0, ra1, rb0, rb1;   // staging registers

    // ---- loader helpers ----
    #define LDG_TILE(kt)                                                       \
        do {                                                                   \
            const float* A_; const float* W_; int k0_, K_;                     \
            if ((kt) < nt1) { A_ = A1; W_ = W1; k0_ = (kt) * BK; K_ = K1; }    \
            else { A_ = A2; W_ = W2; k0_ = ((kt) - nt1) * BK; K_ = K2; }       \
            const float* Ap = A_ + (size_t)(bm * BM + lrow) * K_ + k0_ + lcol; \
            const float* Wp = W_ + (size_t)(bn * BN + lrow) * K_ + k0_ + lcol; \
            ra0 = *(const float4*)Ap;                                          \
            ra1 = *(const float4*)(Ap + (size_t)64 * K_);                      \
            rb0 = *(const float4*)Wp;                                          \
            rb1 = *(const float4*)(Wp + (size_t)64 * K_);                      \
        } while (0)

    #define STS_TILE(buf)                                                      \
        do {                                                                   \
            As[buf][lcol + 0][lrow] = ra0.x; As[buf][lcol + 1][lrow] = ra0.y;  \
            As[buf][lcol + 2][lrow] = ra0.z; As[buf][lcol + 3][lrow] = ra0.w;  \
            As[buf][lcol + 0][lrow + 64] = ra1.x;                              \
            As[buf][lcol + 1][lrow + 64] = ra1.y;                              \
            As[buf][lcol + 2][lrow + 64] = ra1.z;                              \
            As[buf][lcol + 3][lrow + 64] = ra1.w;                              \
            Bs[buf][lcol + 0][lrow] = rb0.x; Bs[buf][lcol + 1][lrow] = rb0.y;  \
            Bs[buf][lcol + 2][lrow] = rb0.z; Bs[buf][lcol + 3][lrow] = rb0.w;  \
            Bs[buf][lcol + 0][lrow + 64] = rb1.x;                              \
            Bs[buf][lcol + 1][lrow + 64] = rb1.y;                              \
            Bs[buf][lcol + 2][lrow + 64] = rb1.z;                              \
            Bs[buf][lcol + 3][lrow + 64] = rb1.w;                              \
        } while (0)

    // ---- prologue: stage tile 0 ----
    LDG_TILE(0);
    STS_TILE(0);
    __syncthreads();

    for (int kt = 0; kt < ntot; ++kt) {
        const int cur = kt & 1;
        const bool more = (kt + 1 < ntot);

        if (more) LDG_TILE(kt + 1);   // in flight during compute below

#pragma unroll
        for (int k = 0; k < BK; ++k) {
            const float4 av0 = *(const float4*)&As[cur][k][ty * TM];
            const float4 av1 = *(const float4*)&As[cur][k][ty * TM + 4];
            const float4 bv0 = *(const float4*)&Bs[cur][k][tx * TN];
            const float4 bv1 = *(const float4*)&Bs[cur][k][tx * TN + 4];
            float a[TM] = {av0.x, av0.y, av0.z, av0.w,
                           av1.x, av1.y, av1.z, av1.w};
            float b[TN] = {bv0.x, bv0.y, bv0.z, bv0.w,
                           bv1.x, bv1.y, bv1.z, bv1.w};
#pragma unroll
            for (int i = 0; i < TM; ++i)
#pragma unroll
                for (int j = 0; j < TN; ++j)
                    acc[i][j] += a[i] * b[j];
        }

        if (more) {
            STS_TILE(cur ^ 1);   // buffer last read at kt-1: all warps passed
            __syncthreads();     // the previous barrier after finishing it
        }
    }

    // ---------------- epilogue ----------------
    const int m0 = bm * BM + ty * TM;
    const int n0 = bn * BN + tx * TN;

    if (mode == 0) {
#pragma unroll
        for (int i = 0; i < TM; ++i) {
            size_t row = (size_t)(m0 + i) * N + n0;
#pragma unroll
            for (int j = 0; j < TN; ++j) {
                float v = acc[i][j];
                if (bias) v += bias[n0 + j];
                Cout[row + j] = v;
            }
        }
    } else {
        unsigned spikes = 0;
#pragma unroll
        for (int i = 0; i < TM; ++i) {
            size_t row = (size_t)(m0 + i) * N + n0;
#pragma unroll
            for (int j = 0; j < TN; ++j) {
                size_t idx = row + j;
                float vold = Vst[idx];
                float iold = Ist[idx];
                float vdec = vold + 0.1f * (iold - vold);     // dt*tau_mem_inv
                float z = (vdec > 1.0f) ? 1.0f : 0.0f;        // v_th = 1
                Vst[idx] = (1.0f - z) * vdec;                 // v_reset = 0
                float idec = iold * 0.8f;                     // 1 - dt*tau_syn_inv
                float inew = (mode == 1) ? ((idec + cin[idx]) + acc[i][j])
                                         : (idec + acc[i][j]);
                Ist[idx] = inew;
                Cout[idx] = z;
                spikes += (unsigned)z;
            }
        }
        if (mode == 2) {
#pragma unroll
            for (int o = 16; o; o >>= 1)
                spikes += __shfl_xor_sync(0xFFFFFFFFu, spikes, o);
            if ((tid & 31) == 0) atomicAdd(cnt, spikes);
        }
    }
}

// ---------------------------------------------------------------------------
// Final: copy last z2 to output, compute firing-rate scalar (bit-exact:
// counts are integers, mean = count * 2^-22, sum in scan order, * 1/16).
// ---------------------------------------------------------------------------
__global__ void finalize(const float* __restrict__ zlast,
                         const unsigned* __restrict__ cnt,
                         float* __restrict__ out, int n, int out_size)
{
    size_t i = (size_t)blockIdx.x * blockDim.x + threadIdx.x;
    size_t stride = (size_t)gridDim.x * blockDim.x;
    for (size_t k = i; k < (size_t)n; k += stride) out[k] = zlast[k];
    if (i == 0 && out_size > n) {
        float rs = 0.f;
        for (int t = 0; t < TW; ++t)
            rs += (float)cnt[t] * (1.0f / 4194304.0f);   // exact: /2^22
        out[n] = rs * (1.0f / 16.0f);                     // inv_T, exact
    }
}

// ---------------------------------------------------------------------------
extern "C" void kernel_launch(void* const* d_in, const int* in_sizes, int n_in,
                              void* d_out, int out_size)
{
    const float* x     = (const float*)d_in[0];
    const float* fc1w  = (const float*)d_in[1];
    const float* fc1b  = (const float*)d_in[2];
    const float* w1in  = (const float*)d_in[3];
    const float* w1rec = (const float*)d_in[4];
    const float* fc2w  = (const float*)d_in[5];
    const float* fc2b  = (const float*)d_in[6];
    const float* w2in  = (const float*)d_in[7];
    const float* w2rec = (const float*)d_in[8];
    (void)in_sizes; (void)n_in;

    float *z0, *c0, *v1, *i1, *z1a, *z1b, *G2, *v2, *i2, *z2a, *z2b;
    unsigned* cnt;
    cudaGetSymbolAddress((void**)&z0,  g_z0);
    cudaGetSymbolAddress((void**)&c0,  g_c0);
    cudaGetSymbolAddress((void**)&v1,  g_v1);
    cudaGetSymbolAddress((void**)&i1,  g_i1);
    cudaGetSymbolAddress((void**)&z1a, g_z1a);
    cudaGetSymbolAddress((void**)&z1b, g_z1b);
    cudaGetSymbolAddress((void**)&G2,  g_G2);
    cudaGetSymbolAddress((void**)&v2,  g_v2);
    cudaGetSymbolAddress((void**)&i2,  g_i2);
    cudaGetSymbolAddress((void**)&z2a, g_z2a);
    cudaGetSymbolAddress((void**)&z2b, g_z2b);
    cudaGetSymbolAddress((void**)&cnt, g_cnt);

    dim3 grid(HH / BN, BSZ / BM);   // (8, 32) = 256 blocks, single wave

    init_state<<<256, 256>>>();

    // z0 = x @ fc1_w^T + fc1_b   (K = 512)
    sgemm_fused<<<grid, NTHR>>>(x, fc1w, nullptr, nullptr, fc1b, nullptr,
                                z0, nullptr, nullptr, nullptr,
                                DD, 0, HH, 0);
    // c0 = z0 @ lif1_win^T       (time-invariant input current, hoisted)
    sgemm_fused<<<grid, NTHR>>>(z0, w1in, nullptr, nullptr, nullptr, nullptr,
                                c0, nullptr, nullptr, nullptr,
                                HH, 0, HH, 0);

    for (int t = 0; t < TW; ++t) {
        float* z1o = (t & 1) ? z1b : z1a;
        float* z1n = (t & 1) ? z1a : z1b;
        float* z2o = (t & 1) ? z2b : z2a;
        float* z2n = (t & 1) ? z2a : z2b;

        // LIF1: acc = z1_old @ w1rec^T ; epilogue: decay/spike/reset,
        //       i1 = (0.8*i1 + c0) + acc, writes z1_new
        sgemm_fused<<<grid, NTHR>>>(z1o, w1rec, nullptr, nullptr, nullptr, c0,
                                    z1n, v1, i1, nullptr,
                                    HH, 0, HH, 1);
        // G2 = z1_new @ fc2_w^T + fc2_b
        sgemm_fused<<<grid, NTHR>>>(z1n, fc2w, nullptr, nullptr, fc2b, nullptr,
                                    G2, nullptr, nullptr, nullptr,
                                    HH, 0, HH, 0);
        // LIF2: acc = G2 @ w2in^T + z2_old @ w2rec^T (dual-K GEMM);
        //       epilogue updates v2/i2, writes z2_new, counts spikes
        sgemm_fused<<<grid, NTHR>>>(G2, w2in, z2o, w2rec, nullptr, nullptr,
                                    z2n, v2, i2, cnt + t,
                                    HH, HH, HH, 2);
    }

    // t = 15 (odd) wrote z2_new into z2a
    finalize<<<512, 256>>>(z2a, cnt, (float*)d_out, NEL, out_size);
}